// round 1
// baseline (speedup 1.0000x reference)
#include <cuda_runtime.h>
#include <cstdint>

// ---------------------------------------------------------------------------
// PatchCoreAnomalyHead: features[8,4096,1024] -> MLP(1024->512 relu ->256)
// -> min_m ||proj - memory_bank[m]||_2  -> out[8,4096]
// R = 32768 rows total, M = 16384 bank entries, D = 256.
// ---------------------------------------------------------------------------

#define R_TOTAL 32768
#define C_IN    1024
#define C_HID   512
#define C_D     256
#define M_BANK  16384

// Scratch (device globals: allocation-free per harness rules)
__device__ float g_H[(size_t)R_TOTAL * C_HID];   // 64 MB
__device__ float g_P[(size_t)R_TOTAL * C_D];     // 32 MB
__device__ float g_m2[M_BANK];

// ------------------------- packed f32x2 helpers ----------------------------
__device__ __forceinline__ unsigned long long pack2(float x, float y) {
    unsigned long long r;
    asm("mov.b64 %0, {%1, %2};" : "=l"(r)
        : "r"(__float_as_uint(x)), "r"(__float_as_uint(y)));
    return r;
}
__device__ __forceinline__ void unpack2(unsigned long long v, float& x, float& y) {
    unsigned int lo, hi;
    asm("mov.b64 {%0, %1}, %2;" : "=r"(lo), "=r"(hi) : "l"(v));
    x = __uint_as_float(lo);
    y = __uint_as_float(hi);
}
__device__ __forceinline__ void fma2(unsigned long long& d,
                                     unsigned long long a,
                                     unsigned long long b) {
    // d = a * b + d   (two packed fp32 lanes) — full-rate fp32 path on sm_10x
    asm("fma.rn.f32x2 %0, %1, %2, %0;" : "+l"(d) : "l"(a), "l"(b));
}

// 8x8 micro-tile step at one k. Ak/Bk point at As[k][0]/Bs[k][0] (128 floats).
// Rows: ty4+0..3 and 64+ty4+0..3. Cols: tx4+0..3 and 64+tx4+0..3 (paired).
__device__ __forceinline__ void micro(const float* __restrict__ Ak,
                                      const float* __restrict__ Bk,
                                      int ty4, int tx4,
                                      unsigned long long (&acc)[8][4]) {
    float4 a0 = *(const float4*)(Ak + ty4);
    float4 a1 = *(const float4*)(Ak + 64 + ty4);
    float4 b0 = *(const float4*)(Bk + tx4);
    float4 b1 = *(const float4*)(Bk + 64 + tx4);
    unsigned long long bp0 = pack2(b0.x, b0.y);
    unsigned long long bp1 = pack2(b0.z, b0.w);
    unsigned long long bp2 = pack2(b1.x, b1.y);
    unsigned long long bp3 = pack2(b1.z, b1.w);
    float av[8] = {a0.x, a0.y, a0.z, a0.w, a1.x, a1.y, a1.z, a1.w};
#pragma unroll
    for (int i = 0; i < 8; i++) {
        unsigned long long ad = pack2(av[i], av[i]);
        fma2(acc[i][0], ad, bp0);
        fma2(acc[i][1], ad, bp1);
        fma2(acc[i][2], ad, bp2);
        fma2(acc[i][3], ad, bp3);
    }
}

// ------------------------- m2 = ||bank row||^2 -----------------------------
__global__ void m2_kernel(const float* __restrict__ MB) {
    int i = blockIdx.x * blockDim.x + threadIdx.x;   // 0..16383
    const float4* p = (const float4*)(MB + (size_t)i * C_D);
    float s = 0.f;
#pragma unroll 8
    for (int q = 0; q < C_D / 4; q++) {
        float4 v = p[q];
        s += v.x * v.x + v.y * v.y + v.z * v.z + v.w * v.w;
    }
    g_m2[i] = s;
}

// ------------------- GEMM: Y = act(X[R,K] @ W[K,N] + b) --------------------
// Block tile 128x128, BK=8, 256 threads, 8x8 per thread via f32x2.
__global__ void __launch_bounds__(256)
mlp_gemm(const float* __restrict__ X, const float* __restrict__ W,
         const float* __restrict__ bias, float* __restrict__ Y,
         int K, int N, int relu) {
    __shared__ float As[8][128];
    __shared__ float Bs[8][128];
    const int t = threadIdx.x;
    const int row0 = blockIdx.y * 128, col0 = blockIdx.x * 128;
    const int tx4 = (t & 15) * 4, ty4 = (t >> 4) * 4;
    const int ar = t >> 1, ak = (t & 1) * 4;     // A-tile load map
    const int bk = t >> 5, bc = (t & 31) * 4;    // B-tile load map

    unsigned long long acc[8][4];
#pragma unroll
    for (int i = 0; i < 8; i++) {
        acc[i][0] = 0ull; acc[i][1] = 0ull; acc[i][2] = 0ull; acc[i][3] = 0ull;
    }

    const float* Ap = X + (size_t)(row0 + ar) * K + ak;
    const float* Bp = W + (size_t)bk * N + col0 + bc;

    for (int k0 = 0; k0 < K; k0 += 8) {
        float4 av = *(const float4*)(Ap + k0);
        float4 bv = *(const float4*)(Bp + (size_t)k0 * N);
        __syncthreads();
        As[ak + 0][ar] = av.x; As[ak + 1][ar] = av.y;
        As[ak + 2][ar] = av.z; As[ak + 3][ar] = av.w;
        *(float4*)&Bs[bk][bc] = bv;
        __syncthreads();
#pragma unroll
        for (int k = 0; k < 8; k++) micro(&As[k][0], &Bs[k][0], ty4, tx4, acc);
    }

#pragma unroll
    for (int i = 0; i < 8; i++) {
        int r = row0 + ty4 + (i & 3) + ((i & 4) ? 64 : 0);
        float v0, v1, v2, v3, v4, v5, v6, v7;
        unpack2(acc[i][0], v0, v1); unpack2(acc[i][1], v2, v3);
        unpack2(acc[i][2], v4, v5); unpack2(acc[i][3], v6, v7);
        int c0 = col0 + tx4, c1 = col0 + 64 + tx4;
        v0 += bias[c0 + 0]; v1 += bias[c0 + 1]; v2 += bias[c0 + 2]; v3 += bias[c0 + 3];
        v4 += bias[c1 + 0]; v5 += bias[c1 + 1]; v6 += bias[c1 + 2]; v7 += bias[c1 + 3];
        if (relu) {
            v0 = fmaxf(v0, 0.f); v1 = fmaxf(v1, 0.f); v2 = fmaxf(v2, 0.f); v3 = fmaxf(v3, 0.f);
            v4 = fmaxf(v4, 0.f); v5 = fmaxf(v5, 0.f); v6 = fmaxf(v6, 0.f); v7 = fmaxf(v7, 0.f);
        }
        *(float4*)&Y[(size_t)r * N + c0] = make_float4(v0, v1, v2, v3);
        *(float4*)&Y[(size_t)r * N + c1] = make_float4(v4, v5, v6, v7);
    }
}

// ------ fused distance: out[r] = sqrt(max(x2[r] + min_m(m2 - 2 p.m), 0)) ---
// One block = 128 rows; P tile (128x256) cached in SMEM; loops all 128
// bank tiles of 128, min folded in the epilogue. No atomics.
__global__ void __launch_bounds__(256)
dist_kernel(const float* __restrict__ P, const float* __restrict__ MB,
            float* __restrict__ out) {
    extern __shared__ char dsm[];
    float (*Asf)[128] = (float(*)[128])dsm;                         // 256x128 = 128 KB
    float (*Bs)[128]  = (float(*)[128])(dsm + 256 * 128 * 4);       // 8x128   = 4 KB
    float* x2s        = (float*)(dsm + 256 * 128 * 4 + 8 * 128 * 4);// 128     = 0.5 KB
    float (*red)[17]  = (float(*)[17])(dsm + 256 * 128 * 4 + 8 * 128 * 4 + 128 * 4);

    const int t = threadIdx.x;
    const int row0 = blockIdx.x * 128;
    const int tx4 = (t & 15) * 4, ty4 = (t >> 4) * 4;
    const int ar = t >> 1;
    const int hk = (t & 1) * 128;

    // Load P tile transposed into SMEM: Asf[k][row]
    {
        const float4* pr = (const float4*)(P + (size_t)(row0 + ar) * C_D + hk);
#pragma unroll
        for (int q = 0; q < 32; q++) {
            float4 v = pr[q];
            int k = hk + q * 4;
            Asf[k + 0][ar] = v.x; Asf[k + 1][ar] = v.y;
            Asf[k + 2][ar] = v.z; Asf[k + 3][ar] = v.w;
        }
    }
    if (t < 128) {
        const float4* pr = (const float4*)(P + (size_t)(row0 + t) * C_D);
        float s = 0.f;
#pragma unroll 8
        for (int q = 0; q < C_D / 4; q++) {
            float4 v = pr[q];
            s += v.x * v.x + v.y * v.y + v.z * v.z + v.w * v.w;
        }
        x2s[t] = s;
    }

    float runmin[8];
#pragma unroll
    for (int i = 0; i < 8; i++) runmin[i] = 3.402823e38f;

    const int br = t >> 1, bq = (t & 1) * 4;
    for (int nt = 0; nt < M_BANK / 128; nt++) {
        unsigned long long acc[8][4];
#pragma unroll
        for (int i = 0; i < 8; i++) {
            acc[i][0] = 0ull; acc[i][1] = 0ull; acc[i][2] = 0ull; acc[i][3] = 0ull;
        }
        const float* Bp = MB + ((size_t)nt * 128 + br) * C_D + bq;
        for (int k0 = 0; k0 < C_D; k0 += 8) {
            float4 bv = *(const float4*)(Bp + k0);
            __syncthreads();   // also orders the Asf/x2s writes before 1st compute
            Bs[bq + 0][br] = bv.x; Bs[bq + 1][br] = bv.y;
            Bs[bq + 2][br] = bv.z; Bs[bq + 3][br] = bv.w;
            __syncthreads();
#pragma unroll
            for (int k = 0; k < 8; k++)
                micro(&Asf[k0 + k][0], &Bs[k][0], ty4, tx4, acc);
        }
        // epilogue: score = m2[c] - 2*dot ; fold into running min
        const float* m2p = g_m2 + nt * 128;
#pragma unroll
        for (int i = 0; i < 8; i++) {
            float v0, v1, v2, v3, v4, v5, v6, v7;
            unpack2(acc[i][0], v0, v1); unpack2(acc[i][1], v2, v3);
            unpack2(acc[i][2], v4, v5); unpack2(acc[i][3], v6, v7);
            float m = runmin[i];
            m = fminf(m, fmaf(-2.f, v0, m2p[tx4 + 0]));
            m = fminf(m, fmaf(-2.f, v1, m2p[tx4 + 1]));
            m = fminf(m, fmaf(-2.f, v2, m2p[tx4 + 2]));
            m = fminf(m, fmaf(-2.f, v3, m2p[tx4 + 3]));
            m = fminf(m, fmaf(-2.f, v4, m2p[64 + tx4 + 0]));
            m = fminf(m, fmaf(-2.f, v5, m2p[64 + tx4 + 1]));
            m = fminf(m, fmaf(-2.f, v6, m2p[64 + tx4 + 2]));
            m = fminf(m, fmaf(-2.f, v7, m2p[64 + tx4 + 3]));
            runmin[i] = m;
        }
    }

    // cross-thread min over the 16 col-groups sharing each row
#pragma unroll
    for (int i = 0; i < 8; i++) {
        int rl = ty4 + (i & 3) + ((i & 4) ? 64 : 0);
        red[rl][t & 15] = runmin[i];
    }
    __syncthreads();
    if (t < 128) {
        float m = red[t][0];
#pragma unroll
        for (int j = 1; j < 16; j++) m = fminf(m, red[t][j]);
        out[row0 + t] = sqrtf(fmaxf(x2s[t] + m, 0.f));
    }
}

// ---------------------------------------------------------------------------
extern "C" void kernel_launch(void* const* d_in, const int* in_sizes, int n_in,
                              void* d_out, int out_size) {
    (void)in_sizes; (void)n_in; (void)out_size;
    const float* features = (const float*)d_in[0];
    const float* W1       = (const float*)d_in[1];
    const float* b1       = (const float*)d_in[2];
    const float* W2       = (const float*)d_in[3];
    const float* b2       = (const float*)d_in[4];
    const float* MB       = (const float*)d_in[5];
    float* out            = (float*)d_out;

    float* H = nullptr;
    float* P = nullptr;
    cudaGetSymbolAddress((void**)&H, g_H);
    cudaGetSymbolAddress((void**)&P, g_P);

    const int DIST_SMEM = 256 * 128 * 4 + 8 * 128 * 4 + 128 * 4 + 128 * 17 * 4;
    cudaFuncSetAttribute(dist_kernel,
                         cudaFuncAttributeMaxDynamicSharedMemorySize, DIST_SMEM);

    m2_kernel<<<M_BANK / 256, 256>>>(MB);
    mlp_gemm<<<dim3(C_HID / 128, R_TOTAL / 128), 256>>>(features, W1, b1, H,
                                                        C_IN, C_HID, 1);
    mlp_gemm<<<dim3(C_D / 128, R_TOTAL / 128), 256>>>(H, W2, b2, P,
                                                      C_HID, C_D, 0);
    dist_kernel<<<R_TOTAL / 128, 256, DIST_SMEM>>>(P, MB, out);
}

// round 3
// speedup vs baseline: 3.0089x; 3.0089x over previous
#include <cuda_runtime.h>
#include <cstdint>

// ---------------------------------------------------------------------------
// PatchCoreAnomalyHead via mma.sync tf32 (sm_100-baseline PTX; tcgen05 is
// unavailable because the harness assembles for sm_100, not sm_100a).
// features[8,4096,1024] -> MLP(1024->512 relu ->256) -> min_m ||p - bank[m]||.
// ---------------------------------------------------------------------------

#define R_TOTAL 32768
#define C_IN    1024
#define C_HID   512
#define C_D     256
#define M_BANK  16384

__device__ float g_H[(size_t)R_TOTAL * C_HID];    // 64 MB
__device__ float g_P[(size_t)R_TOTAL * C_D];      // 32 MB
__device__ float g_W1T[(size_t)C_HID * C_IN];     // 2 MB   (W1^T: [512,1024])
__device__ float g_W2T[(size_t)C_D * C_HID];      // 0.5 MB (W2^T: [256,512])
__device__ float g_m2[M_BANK];

// ---------------------- m16n8k8 tf32 MMA ----------------------------------
__device__ __forceinline__ void mma_tf32(float (&d)[4],
                                         const uint32_t (&a)[4],
                                         const uint32_t (&b)[2]) {
    asm volatile(
        "mma.sync.aligned.m16n8k8.row.col.f32.tf32.tf32.f32 "
        "{%0,%1,%2,%3}, {%4,%5,%6,%7}, {%8,%9}, {%0,%1,%2,%3};"
        : "+f"(d[0]), "+f"(d[1]), "+f"(d[2]), "+f"(d[3])
        : "r"(a[0]), "r"(a[1]), "r"(a[2]), "r"(a[3]), "r"(b[0]), "r"(b[1]));
}

// Compute a k=64 slab: warp tile 64x32 (4 m-tiles x 4 n-tiles of m16n8k8).
// aw -> A row (rbase + t/4), col t%4;  bw -> B row (nbase + t/4), col t%4.
// Row strides ALD/BLD are template constants, chosen ≡ 4 (mod 32) banks so
// every fragment gather is bank-conflict-free.
template <int ALD, int BLD>
__device__ __forceinline__ void compute_k64(const float* __restrict__ aw,
                                            const float* __restrict__ bw,
                                            float (&acc)[4][4][4]) {
#pragma unroll
    for (int s = 0; s < 8; s++) {
        const int k0 = s * 8;
        uint32_t a[4][4], b[4][2];
#pragma unroll
        for (int mi = 0; mi < 4; mi++) {
            const uint32_t* p = (const uint32_t*)(aw + mi * 16 * ALD + k0);
            a[mi][0] = p[0];
            a[mi][1] = p[8 * ALD];
            a[mi][2] = p[4];
            a[mi][3] = p[8 * ALD + 4];
        }
#pragma unroll
        for (int ni = 0; ni < 4; ni++) {
            const uint32_t* p = (const uint32_t*)(bw + ni * 8 * BLD + k0);
            b[ni][0] = p[0];
            b[ni][1] = p[4];
        }
#pragma unroll
        for (int mi = 0; mi < 4; mi++)
#pragma unroll
            for (int ni = 0; ni < 4; ni++)
                mma_tf32(acc[mi][ni], a[mi], b[ni]);
    }
}

// ------------------------- small prep kernels ------------------------------
__global__ void m2_kernel(const float* __restrict__ MBp) {
    int i = blockIdx.x * blockDim.x + threadIdx.x;
    const float4* p = (const float4*)(MBp + (size_t)i * C_D);
    float s = 0.f;
#pragma unroll 8
    for (int q = 0; q < C_D / 4; q++) {
        float4 v = p[q];
        s += v.x * v.x + v.y * v.y + v.z * v.z + v.w * v.w;
    }
    g_m2[i] = s;
}

// dst[C x R] = src[R x C]^T
__global__ void transpose32(const float* __restrict__ src, float* __restrict__ dst,
                            int R, int C) {
    __shared__ float tile[32][33];
    int bx = blockIdx.x * 32, by = blockIdx.y * 32;
    int tx = threadIdx.x & 31, ty = threadIdx.x >> 5;   // 256 threads
#pragma unroll
    for (int i = 0; i < 32; i += 8)
        tile[ty + i][tx] = src[(size_t)(by + ty + i) * C + bx + tx];
    __syncthreads();
#pragma unroll
    for (int i = 0; i < 32; i += 8)
        dst[(size_t)(bx + ty + i) * R + by + tx] = tile[tx][ty + i];
}

// ------------------- MLP GEMM: Y = act(X @ WT^T + bias) --------------------
// X:[R,K] row-major, WT:[N,K] row-major. CTA 128x128, k64 chunks, double buf.
#define CH_LD   68
#define CH_SZ   (128 * CH_LD * 4)     // 34816 B per chunk buffer

__global__ void __launch_bounds__(256)
mlp_tc(const float* __restrict__ X, const float* __restrict__ WT,
       const float* __restrict__ bias, float* __restrict__ Y,
       int K, int N, int relu) {
    extern __shared__ char sm[];
    float* Ab[2] = {(float*)sm, (float*)(sm + CH_SZ)};
    float* Bb[2] = {(float*)(sm + 2 * CH_SZ), (float*)(sm + 3 * CH_SZ)};

    const int t = threadIdx.x, w = t >> 5, q = (t & 31) >> 2, c = t & 3;
    const int wr = w & 1, wc = w >> 1;
    const int row0 = blockIdx.y * 128, col0 = blockIdx.x * 128;
    const int r = t >> 4, kq = (t & 15) * 4;      // copy map: 16 rows/iter

    float acc[4][4][4];
#pragma unroll
    for (int mi = 0; mi < 4; mi++)
#pragma unroll
        for (int ni = 0; ni < 4; ni++)
#pragma unroll
            for (int e = 0; e < 4; e++) acc[mi][ni][e] = 0.f;

    const int nch = K / 64;
    for (int j = 0; j < nch; j++) {
        float* ab = Ab[j & 1];
        float* bb = Bb[j & 1];
#pragma unroll
        for (int i = 0; i < 8; i++) {
            int rr = r + i * 16;
            *(float4*)(ab + rr * CH_LD + kq) =
                *(const float4*)(X + (size_t)(row0 + rr) * K + j * 64 + kq);
            *(float4*)(bb + rr * CH_LD + kq) =
                *(const float4*)(WT + (size_t)(col0 + rr) * K + j * 64 + kq);
        }
        __syncthreads();
        compute_k64<CH_LD, CH_LD>(ab + (wr * 64 + q) * CH_LD + c,
                                  bb + (wc * 32 + q) * CH_LD + c, acc);
    }

    // epilogue: bias + optional relu, direct stores
#pragma unroll
    for (int mi = 0; mi < 4; mi++) {
        int rg = row0 + wr * 64 + mi * 16 + q;
#pragma unroll
        for (int ni = 0; ni < 4; ni++) {
            int cg = col0 + wc * 32 + ni * 8 + 2 * c;
            float2 bv = *(const float2*)(bias + cg);
            float v0 = acc[mi][ni][0] + bv.x;
            float v1 = acc[mi][ni][1] + bv.y;
            float v2 = acc[mi][ni][2] + bv.x;
            float v3 = acc[mi][ni][3] + bv.y;
            if (relu) {
                v0 = fmaxf(v0, 0.f); v1 = fmaxf(v1, 0.f);
                v2 = fmaxf(v2, 0.f); v3 = fmaxf(v3, 0.f);
            }
            *(float2*)&Y[(size_t)rg * N + cg] = make_float2(v0, v1);
            *(float2*)&Y[(size_t)(rg + 8) * N + cg] = make_float2(v2, v3);
        }
    }
}

// ---------------- fused distance + min (mma.sync tf32) ---------------------
// One CTA = 128 rows of P stationary in SMEM; bank streamed in k64 chunks
// (double-buffered, one sync per chunk); per-tile min folded from registers.
#define AS_LD   260
#define AS_SZ   (128 * AS_LD * 4)                 // 133120
#define DB0_OFF AS_SZ                             // 133120
#define DB1_OFF (AS_SZ + CH_SZ)                   // 167936
#define X2_OFF  (AS_SZ + 2 * CH_SZ)               // 202752
#define RED_OFF (X2_OFF + 512)                    // 203264
#define DIST_SMEM (RED_OFF + 4 * 128 * 4)         // 205312

__global__ void __launch_bounds__(256)
dist_tc(const float* __restrict__ P, const float* __restrict__ MBp,
        float* __restrict__ out) {
    extern __shared__ char sm[];
    float* As = (float*)sm;                          // [128][260]
    float* Bb[2] = {(float*)(sm + DB0_OFF), (float*)(sm + DB1_OFF)};
    float* x2s = (float*)(sm + X2_OFF);              // [128]
    float* red = (float*)(sm + RED_OFF);             // [4][128]

    const int t = threadIdx.x, w = t >> 5, q = (t & 31) >> 2, c = t & 3;
    const int wr = w & 1, wc = w >> 1;
    const int row0 = blockIdx.x * 128;

    // stationary P tile (coalesced, natural layout)
#pragma unroll
    for (int i = 0; i < 32; i++) {
        int f = t + i * 256;
        int rr = f >> 6, cq = (f & 63) * 4;
        *(float4*)(As + rr * AS_LD + cq) =
            *(const float4*)(P + (size_t)(row0 + rr) * C_D + cq);
    }
    if (t < 128) {
        const float4* pr = (const float4*)(P + (size_t)(row0 + t) * C_D);
        float s = 0.f;
#pragma unroll 8
        for (int u = 0; u < C_D / 4; u++) {
            float4 v = pr[u];
            s += v.x * v.x + v.y * v.y + v.z * v.z + v.w * v.w;
        }
        x2s[t] = s;
    }

    const float* aw0 = As + (wr * 64 + q) * AS_LD + c;
    const int r = t >> 4, kq = (t & 15) * 4;

    float runmin[4][2];
#pragma unroll
    for (int mi = 0; mi < 4; mi++) { runmin[mi][0] = 3.402823e38f; runmin[mi][1] = 3.402823e38f; }

    for (int nt = 0; nt < M_BANK / 128; nt++) {
        float acc[4][4][4];
#pragma unroll
        for (int mi = 0; mi < 4; mi++)
#pragma unroll
            for (int ni = 0; ni < 4; ni++)
#pragma unroll
                for (int e = 0; e < 4; e++) acc[mi][ni][e] = 0.f;

        for (int kc = 0; kc < 4; kc++) {
            int j = nt * 4 + kc;
            float* bb = Bb[j & 1];
#pragma unroll
            for (int i = 0; i < 8; i++) {
                int rr = r + i * 16;
                *(float4*)(bb + rr * CH_LD + kq) =
                    *(const float4*)(MBp + (size_t)(nt * 128 + rr) * C_D + kc * 64 + kq);
            }
            __syncthreads();
            compute_k64<AS_LD, CH_LD>(aw0 + kc * 64,
                                      bb + (wc * 32 + q) * CH_LD + c, acc);
        }

        // fold min(m2 - 2*dot) for this bank tile
        const float* m2p = g_m2 + nt * 128 + wc * 32 + 2 * c;
#pragma unroll
        for (int mi = 0; mi < 4; mi++) {
            float m0 = runmin[mi][0], m1 = runmin[mi][1];
#pragma unroll
            for (int ni = 0; ni < 4; ni++) {
                float2 m2v = *(const float2*)(m2p + ni * 8);
                m0 = fminf(m0, fmaf(-2.f, acc[mi][ni][0], m2v.x));
                m0 = fminf(m0, fmaf(-2.f, acc[mi][ni][1], m2v.y));
                m1 = fminf(m1, fmaf(-2.f, acc[mi][ni][2], m2v.x));
                m1 = fminf(m1, fmaf(-2.f, acc[mi][ni][3], m2v.y));
            }
            runmin[mi][0] = m0; runmin[mi][1] = m1;
        }
    }

    // lane reduction over t%4 (same rows), then cross-warp via smem
#pragma unroll
    for (int mi = 0; mi < 4; mi++)
#pragma unroll
        for (int s = 0; s < 2; s++) {
            float v = runmin[mi][s];
            v = fminf(v, __shfl_xor_sync(0xffffffffu, v, 1));
            v = fminf(v, __shfl_xor_sync(0xffffffffu, v, 2));
            if (c == 0) red[wc * 128 + wr * 64 + mi * 16 + 8 * s + q] = v;
        }
    __syncthreads();
    if (t < 128) {
        float m = fminf(fminf(red[t], red[128 + t]), fminf(red[256 + t], red[384 + t]));
        out[row0 + t] = sqrtf(fmaxf(x2s[t] + m, 0.f));
    }
}

// ---------------------------------------------------------------------------
extern "C" void kernel_launch(void* const* d_in, const int* in_sizes, int n_in,
                              void* d_out, int out_size) {
    (void)in_sizes; (void)n_in; (void)out_size;
    const float* features = (const float*)d_in[0];
    const float* W1       = (const float*)d_in[1];
    const float* b1       = (const float*)d_in[2];
    const float* W2       = (const float*)d_in[3];
    const float* b2       = (const float*)d_in[4];
    const float* MBp      = (const float*)d_in[5];
    float* out            = (float*)d_out;

    float *H, *Pp, *W1T, *W2T;
    cudaGetSymbolAddress((void**)&H, g_H);
    cudaGetSymbolAddress((void**)&Pp, g_P);
    cudaGetSymbolAddress((void**)&W1T, g_W1T);
    cudaGetSymbolAddress((void**)&W2T, g_W2T);

    const int MLP_SMEM = 4 * CH_SZ;                  // 139264
    cudaFuncSetAttribute(mlp_tc, cudaFuncAttributeMaxDynamicSharedMemorySize, MLP_SMEM);
    cudaFuncSetAttribute(dist_tc, cudaFuncAttributeMaxDynamicSharedMemorySize, DIST_SMEM);

    transpose32<<<dim3(C_HID / 32, C_IN / 32), 256>>>(W1, W1T, C_IN, C_HID);
    transpose32<<<dim3(C_D / 32, C_HID / 32), 256>>>(W2, W2T, C_HID, C_D);
    m2_kernel<<<M_BANK / 256, 256>>>(MBp);
    mlp_tc<<<dim3(C_HID / 128, R_TOTAL / 128), 256, MLP_SMEM>>>(features, W1T, b1, H,
                                                                C_IN, C_HID, 1);
    mlp_tc<<<dim3(C_D / 128, R_TOTAL / 128), 256, MLP_SMEM>>>(H, W2T, b2, Pp,
                                                              C_HID, C_D, 0);
    dist_tc<<<R_TOTAL / 128, 256, DIST_SMEM>>>(Pp, MBp, out);
}

// round 4
// speedup vs baseline: 4.1886x; 1.3921x over previous
#include <cuda_runtime.h>
#include <cstdint>

// ---------------------------------------------------------------------------
// PatchCoreAnomalyHead via mma.sync tf32 + cp.async pipelines (sm_100 PTX).
// features[8,4096,1024] -> MLP(1024->512 relu ->256) -> min_m ||p - bank[m]||.
// ---------------------------------------------------------------------------

#define R_TOTAL 32768
#define C_IN    1024
#define C_HID   512
#define C_D     256
#define M_BANK  16384

__device__ float g_H[(size_t)R_TOTAL * C_HID];    // 64 MB
__device__ float g_P[(size_t)R_TOTAL * C_D];      // 32 MB
__device__ float g_W1T[(size_t)C_HID * C_IN];     // W1^T [512,1024]
__device__ float g_W2T[(size_t)C_D * C_HID];      // W2^T [256,512]
__device__ float g_m2[M_BANK];
__device__ float g_x2[R_TOTAL];
__device__ float g_pmin[4 * R_TOTAL];             // per-bank-quarter partial mins

// ---------------------------- helpers --------------------------------------
__device__ __forceinline__ uint32_t smem_u32(const void* p) {
    uint32_t a;
    asm("{ .reg .u64 t; cvta.to.shared.u64 t, %1; cvt.u32.u64 %0, t; }"
        : "=r"(a) : "l"(p));
    return a;
}
__device__ __forceinline__ void cp16(uint32_t dst, const void* src) {
    asm volatile("cp.async.cg.shared.global [%0], [%1], 16;" :: "r"(dst), "l"(src));
}
#define CP_COMMIT() asm volatile("cp.async.commit_group;" ::: "memory")
#define CP_WAIT(n)  asm volatile("cp.async.wait_group %0;" :: "n"(n) : "memory")

__device__ __forceinline__ void mma_tf32(float (&d)[4],
                                         const uint32_t (&a)[4],
                                         const uint32_t (&b)[2]) {
    asm volatile(
        "mma.sync.aligned.m16n8k8.row.col.f32.tf32.tf32.f32 "
        "{%0,%1,%2,%3}, {%4,%5,%6,%7}, {%8,%9}, {%0,%1,%2,%3};"
        : "+f"(d[0]), "+f"(d[1]), "+f"(d[2]), "+f"(d[3])
        : "r"(a[0]), "r"(a[1]), "r"(a[2]), "r"(a[3]), "r"(b[0]), "r"(b[1]));
}

// k=32 slab, warp tile 64x64 (4 m-tiles x 8 n-tiles of m16n8k8).
// aw = A base + (rowband + q)*ALD + c ;  bw = B base + (colband + q)*BLD + c.
// ALD,BLD ≡ 4 (mod 32) -> all fragment gathers bank-conflict-free.
template <int ALD, int BLD>
__device__ __forceinline__ void compute_k32(const float* __restrict__ aw,
                                            const float* __restrict__ bw,
                                            float (&acc)[4][8][4]) {
#pragma unroll
    for (int s = 0; s < 4; s++) {
        const int k0 = s * 8;
        uint32_t a[4][4], b[8][2];
#pragma unroll
        for (int mi = 0; mi < 4; mi++) {
            const uint32_t* p = (const uint32_t*)(aw + mi * 16 * ALD + k0);
            a[mi][0] = p[0];
            a[mi][1] = p[8 * ALD];
            a[mi][2] = p[4];
            a[mi][3] = p[8 * ALD + 4];
        }
#pragma unroll
        for (int ni = 0; ni < 8; ni++) {
            const uint32_t* p = (const uint32_t*)(bw + ni * 8 * BLD + k0);
            b[ni][0] = p[0];
            b[ni][1] = p[4];
        }
#pragma unroll
        for (int mi = 0; mi < 4; mi++)
#pragma unroll
            for (int ni = 0; ni < 8; ni++)
                mma_tf32(acc[mi][ni], a[mi], b[ni]);
    }
}

// ------------------------- small prep kernels ------------------------------
__global__ void rowsq_kernel(const float* __restrict__ src, float* __restrict__ dst) {
    int i = blockIdx.x * blockDim.x + threadIdx.x;
    const float4* p = (const float4*)(src + (size_t)i * C_D);
    float s = 0.f;
#pragma unroll 8
    for (int q = 0; q < C_D / 4; q++) {
        float4 v = p[q];
        s += v.x * v.x + v.y * v.y + v.z * v.z + v.w * v.w;
    }
    dst[i] = s;
}
__global__ void transpose32(const float* __restrict__ src, float* __restrict__ dst,
                            int R, int C) {
    __shared__ float tile[32][33];
    int bx = blockIdx.x * 32, by = blockIdx.y * 32;
    int tx = threadIdx.x & 31, ty = threadIdx.x >> 5;
#pragma unroll
    for (int i = 0; i < 32; i += 8)
        tile[ty + i][tx] = src[(size_t)(by + ty + i) * C + bx + tx];
    __syncthreads();
#pragma unroll
    for (int i = 0; i < 32; i += 8)
        dst[(size_t)(bx + ty + i) * R + by + tx] = tile[tx][ty + i];
}

// ------------------- MLP GEMM: Y = act(X @ WT^T + bias) --------------------
// CTA tile 128x256, warp 64x64, k32 chunks, cp.async double-buffered.
#define LDK    36
#define ACH_SZ (128 * LDK * 4)       // 18432
#define BCH_SZ (256 * LDK * 4)       // 36864
#define MLP_SMEM (2 * ACH_SZ + 2 * BCH_SZ)   // 110592

__global__ void __launch_bounds__(256)
mlp_tc(const float* __restrict__ X, const float* __restrict__ WT,
       const float* __restrict__ bias, float* __restrict__ Y,
       int K, int N, int relu) {
    extern __shared__ char sm[];
    const uint32_t sbase = smem_u32(sm);
    const uint32_t Aoff[2] = {0u, ACH_SZ};
    const uint32_t Boff[2] = {2 * ACH_SZ, 2 * ACH_SZ + BCH_SZ};

    const int t = threadIdx.x, w = t >> 5, q = (t & 31) >> 2, c = t & 3;
    const int wr = w & 1, wc = w >> 1;
    const int row0 = blockIdx.y * 128, col0 = blockIdx.x * 256;
    const int cr = t >> 3, c4 = (t & 7) * 4;    // copy map: 32 rows per pass

    float acc[4][8][4];
#pragma unroll
    for (int mi = 0; mi < 4; mi++)
#pragma unroll
        for (int ni = 0; ni < 8; ni++)
#pragma unroll
            for (int e = 0; e < 4; e++) acc[mi][ni][e] = 0.f;

    auto copy_chunk = [&](int j, int buf) {
#pragma unroll
        for (int i = 0; i < 4; i++) {   // A: 128 rows
            int rr = cr + i * 32;
            cp16(sbase + Aoff[buf] + (uint32_t)(rr * LDK + c4) * 4,
                 X + (size_t)(row0 + rr) * K + j * 32 + c4);
        }
#pragma unroll
        for (int i = 0; i < 8; i++) {   // B: 256 rows
            int rr = cr + i * 32;
            cp16(sbase + Boff[buf] + (uint32_t)(rr * LDK + c4) * 4,
                 WT + (size_t)(col0 + rr) * K + j * 32 + c4);
        }
    };

    const int nch = K / 32;
    copy_chunk(0, 0);
    CP_COMMIT();
    for (int j = 0; j < nch; j++) {
        if (j + 1 < nch) { copy_chunk(j + 1, (j + 1) & 1); CP_COMMIT(); CP_WAIT(1); }
        else             { CP_WAIT(0); }
        __syncthreads();
        const float* ab = (const float*)(sm + Aoff[j & 1]);
        const float* bb = (const float*)(sm + Boff[j & 1]);
        compute_k32<LDK, LDK>(ab + (wr * 64 + q) * LDK + c,
                              bb + (wc * 64 + q) * LDK + c, acc);
        __syncthreads();
    }

#pragma unroll
    for (int mi = 0; mi < 4; mi++) {
        int rg = row0 + wr * 64 + mi * 16 + q;
#pragma unroll
        for (int ni = 0; ni < 8; ni++) {
            int cg = col0 + wc * 64 + ni * 8 + 2 * c;
            float2 bv = *(const float2*)(bias + cg);
            float v0 = acc[mi][ni][0] + bv.x;
            float v1 = acc[mi][ni][1] + bv.y;
            float v2 = acc[mi][ni][2] + bv.x;
            float v3 = acc[mi][ni][3] + bv.y;
            if (relu) {
                v0 = fmaxf(v0, 0.f); v1 = fmaxf(v1, 0.f);
                v2 = fmaxf(v2, 0.f); v3 = fmaxf(v3, 0.f);
            }
            *(float2*)&Y[(size_t)rg * N + cg] = make_float2(v0, v1);
            *(float2*)&Y[(size_t)(rg + 8) * N + cg] = make_float2(v2, v3);
        }
    }
}

// ---------------- fused distance + partial min ------------------------------
// CTA = (bank quarter, 128-row tile). P tile stationary; bank quarter streamed
// in 256-entry n-tiles x 8 k32 chunks, cp.async double-buffered.
#define AS_LD   260
#define AS_SZ   (128 * AS_LD * 4)                 // 133120
#define DB0_OFF AS_SZ
#define DB1_OFF (AS_SZ + BCH_SZ)
#define RED_OFF (AS_SZ + 2 * BCH_SZ)              // 206848
#define DIST_SMEM (RED_OFF + 4 * 128 * 4)         // 208896

__global__ void __launch_bounds__(256)
dist_tc(const float* __restrict__ P, const float* __restrict__ MBp) {
    extern __shared__ char sm[];
    const uint32_t sbase = smem_u32(sm);
    float* As = (float*)sm;
    const uint32_t Boff[2] = {DB0_OFF, DB1_OFF};
    float* red = (float*)(sm + RED_OFF);

    const int t = threadIdx.x, w = t >> 5, q = (t & 31) >> 2, c = t & 3;
    const int wr = w & 1, wc = w >> 1;
    const int row0 = blockIdx.y * 128;
    const int qbase = blockIdx.x * (M_BANK / 4);  // bank quarter
    const int cr = t >> 3, c4 = (t & 7) * 4;

    // stationary P tile [128][260]
#pragma unroll
    for (int i = 0; i < 32; i++) {
        int f = t + i * 256;
        int rr = f >> 6, cq = (f & 63) * 4;
        *(float4*)(As + rr * AS_LD + cq) =
            *(const float4*)(P + (size_t)(row0 + rr) * C_D + cq);
    }

    auto copy_chunk = [&](int jj, int buf) {
        int nt = jj >> 3, kc = jj & 7;
#pragma unroll
        for (int i = 0; i < 8; i++) {   // 256 bank rows x 32 k
            int rr = cr + i * 32;
            cp16(sbase + Boff[buf] + (uint32_t)(rr * LDK + c4) * 4,
                 MBp + (size_t)(qbase + nt * 256 + rr) * C_D + kc * 32 + c4);
        }
    };

    float acc[4][8][4];
#pragma unroll
    for (int mi = 0; mi < 4; mi++)
#pragma unroll
        for (int ni = 0; ni < 8; ni++)
#pragma unroll
            for (int e = 0; e < 4; e++) acc[mi][ni][e] = 0.f;
    float runmin[4][2];
#pragma unroll
    for (int mi = 0; mi < 4; mi++) { runmin[mi][0] = 3.402823e38f; runmin[mi][1] = 3.402823e38f; }

    const float* aw0 = As + (wr * 64 + q) * AS_LD + c;

    copy_chunk(0, 0);
    CP_COMMIT();
    const int NCH = (M_BANK / 4 / 256) * 8;       // 128 chunks
    for (int jj = 0; jj < NCH; jj++) {
        if (jj + 1 < NCH) { copy_chunk(jj + 1, (jj + 1) & 1); CP_COMMIT(); CP_WAIT(1); }
        else              { CP_WAIT(0); }
        __syncthreads();
        const int kc = jj & 7;
        const float* bb = (const float*)(sm + Boff[jj & 1]);
        compute_k32<AS_LD, LDK>(aw0 + kc * 32, bb + (wc * 64 + q) * LDK + c, acc);
        __syncthreads();
        if (kc == 7) {
            const int nt = jj >> 3;
            const float* m2p = g_m2 + qbase + nt * 256 + wc * 64 + 2 * c;
#pragma unroll
            for (int mi = 0; mi < 4; mi++) {
                float m0 = runmin[mi][0], m1 = runmin[mi][1];
#pragma unroll
                for (int ni = 0; ni < 8; ni++) {
                    float2 m2v = *(const float2*)(m2p + ni * 8);
                    m0 = fminf(m0, fmaf(-2.f, acc[mi][ni][0], m2v.x));
                    m0 = fminf(m0, fmaf(-2.f, acc[mi][ni][1], m2v.y));
                    m1 = fminf(m1, fmaf(-2.f, acc[mi][ni][2], m2v.x));
                    m1 = fminf(m1, fmaf(-2.f, acc[mi][ni][3], m2v.y));
                    acc[mi][ni][0] = 0.f; acc[mi][ni][1] = 0.f;
                    acc[mi][ni][2] = 0.f; acc[mi][ni][3] = 0.f;
                }
                runmin[mi][0] = m0; runmin[mi][1] = m1;
            }
        }
    }

    // reduce over the 4 lanes (c) sharing each row, then over the 4 col-band warps
#pragma unroll
    for (int mi = 0; mi < 4; mi++)
#pragma unroll
        for (int s = 0; s < 2; s++) {
            float v = runmin[mi][s];
            v = fminf(v, __shfl_xor_sync(0xffffffffu, v, 1));
            v = fminf(v, __shfl_xor_sync(0xffffffffu, v, 2));
            if (c == 0) red[wc * 128 + wr * 64 + mi * 16 + s * 8 + q] = v;
        }
    __syncthreads();
    if (t < 128) {
        float m = fminf(fminf(red[t], red[128 + t]), fminf(red[256 + t], red[384 + t]));
        g_pmin[(size_t)blockIdx.x * R_TOTAL + row0 + t] = m;
    }
}

// ------------------------------ combine ------------------------------------
__global__ void combine_kernel(float* __restrict__ out) {
    int r = blockIdx.x * blockDim.x + threadIdx.x;
    float m = fminf(fminf(g_pmin[r], g_pmin[R_TOTAL + r]),
                    fminf(g_pmin[2 * R_TOTAL + r], g_pmin[3 * R_TOTAL + r]));
    out[r] = sqrtf(fmaxf(g_x2[r] + m, 0.f));
}

// ---------------------------------------------------------------------------
extern "C" void kernel_launch(void* const* d_in, const int* in_sizes, int n_in,
                              void* d_out, int out_size) {
    (void)in_sizes; (void)n_in; (void)out_size;
    const float* features = (const float*)d_in[0];
    const float* W1       = (const float*)d_in[1];
    const float* b1       = (const float*)d_in[2];
    const float* W2       = (const float*)d_in[3];
    const float* b2       = (const float*)d_in[4];
    const float* MBp      = (const float*)d_in[5];
    float* out            = (float*)d_out;

    float *H, *Pp, *W1T, *W2T, *m2p, *x2p;
    cudaGetSymbolAddress((void**)&H, g_H);
    cudaGetSymbolAddress((void**)&Pp, g_P);
    cudaGetSymbolAddress((void**)&W1T, g_W1T);
    cudaGetSymbolAddress((void**)&W2T, g_W2T);
    cudaGetSymbolAddress((void**)&m2p, g_m2);
    cudaGetSymbolAddress((void**)&x2p, g_x2);

    cudaFuncSetAttribute(mlp_tc, cudaFuncAttributeMaxDynamicSharedMemorySize, MLP_SMEM);
    cudaFuncSetAttribute(dist_tc, cudaFuncAttributeMaxDynamicSharedMemorySize, DIST_SMEM);

    transpose32<<<dim3(C_HID / 32, C_IN / 32), 256>>>(W1, W1T, C_IN, C_HID);
    transpose32<<<dim3(C_D / 32, C_HID / 32), 256>>>(W2, W2T, C_HID, C_D);
    rowsq_kernel<<<M_BANK / 256, 256>>>(MBp, m2p);
    mlp_tc<<<dim3(C_HID / 256, R_TOTAL / 128), 256, MLP_SMEM>>>(features, W1T, b1, H,
                                                                C_IN, C_HID, 1);
    mlp_tc<<<dim3(C_D / 256, R_TOTAL / 128), 256, MLP_SMEM>>>(H, W2T, b2, Pp,
                                                              C_HID, C_D, 0);
    rowsq_kernel<<<R_TOTAL / 256, 256>>>(Pp, x2p);
    dist_tc<<<dim3(4, R_TOTAL / 128), 256, DIST_SMEM>>>(Pp, MBp);
    combine_kernel<<<R_TOTAL / 256, 256>>>(out);
}

// round 5
// speedup vs baseline: 4.3868x; 1.0473x over previous
#include <cuda_runtime.h>
#include <cstdint>

// ---------------------------------------------------------------------------
// PatchCoreAnomalyHead via mma.sync tf32 + cp.async pipelines (sm_100 PTX).
// features[8,4096,1024] -> MLP(1024->512 relu ->256) -> min_m ||p - bank[m]||.
// ---------------------------------------------------------------------------

#define R_TOTAL 32768
#define C_IN    1024
#define C_HID   512
#define C_D     256
#define M_BANK  16384

__device__ float g_H[(size_t)R_TOTAL * C_HID];
__device__ float g_P[(size_t)R_TOTAL * C_D];
__device__ float g_W1T[(size_t)C_HID * C_IN];
__device__ float g_W2T[(size_t)C_D * C_HID];
__device__ float g_m2[M_BANK];
__device__ float g_x2[R_TOTAL];
__device__ float g_pmin[4 * R_TOTAL];

// ---------------------------- helpers --------------------------------------
__device__ __forceinline__ uint32_t smem_u32(const void* p) {
    uint32_t a;
    asm("{ .reg .u64 t; cvta.to.shared.u64 t, %1; cvt.u32.u64 %0, t; }"
        : "=r"(a) : "l"(p));
    return a;
}
__device__ __forceinline__ void cp16(uint32_t dst, const void* src) {
    asm volatile("cp.async.cg.shared.global [%0], [%1], 16;" :: "r"(dst), "l"(src));
}
#define CP_COMMIT() asm volatile("cp.async.commit_group;" ::: "memory")
#define CP_WAIT0()  asm volatile("cp.async.wait_group 0;" ::: "memory")

__device__ __forceinline__ void mma_tf32(float (&d)[4],
                                         const uint32_t (&a)[4],
                                         const uint32_t (&b)[2]) {
    asm volatile(
        "mma.sync.aligned.m16n8k8.row.col.f32.tf32.tf32.f32 "
        "{%0,%1,%2,%3}, {%4,%5,%6,%7}, {%8,%9}, {%0,%1,%2,%3};"
        : "+f"(d[0]), "+f"(d[1]), "+f"(d[2]), "+f"(d[3])
        : "r"(a[0]), "r"(a[1]), "r"(a[2]), "r"(a[3]), "r"(b[0]), "r"(b[1]));
}

// k=32 slab, warp tile 64x64 (4 m x 8 n of m16n8k8).
// ALD,BLD ≡ 4 (mod 32) -> all fragment gathers bank-conflict-free.
template <int ALD, int BLD>
__device__ __forceinline__ void compute_k32(const float* __restrict__ aw,
                                            const float* __restrict__ bw,
                                            float (&acc)[4][8][4]) {
#pragma unroll
    for (int s = 0; s < 4; s++) {
        const int k0 = s * 8;
        uint32_t a[4][4], b[8][2];
#pragma unroll
        for (int mi = 0; mi < 4; mi++) {
            const uint32_t* p = (const uint32_t*)(aw + mi * 16 * ALD + k0);
            a[mi][0] = p[0];
            a[mi][1] = p[8 * ALD];
            a[mi][2] = p[4];
            a[mi][3] = p[8 * ALD + 4];
        }
#pragma unroll
        for (int ni = 0; ni < 8; ni++) {
            const uint32_t* p = (const uint32_t*)(bw + ni * 8 * BLD + k0);
            b[ni][0] = p[0];
            b[ni][1] = p[4];
        }
#pragma unroll
        for (int mi = 0; mi < 4; mi++)
#pragma unroll
            for (int ni = 0; ni < 8; ni++)
                mma_tf32(acc[mi][ni], a[mi], b[ni]);
    }
}

// ------------------------- small prep kernels ------------------------------
__global__ void rowsq_kernel(const float* __restrict__ src, float* __restrict__ dst) {
    int i = blockIdx.x * blockDim.x + threadIdx.x;
    const float4* p = (const float4*)(src + (size_t)i * C_D);
    float s = 0.f;
#pragma unroll 8
    for (int q = 0; q < C_D / 4; q++) {
        float4 v = p[q];
        s += v.x * v.x + v.y * v.y + v.z * v.z + v.w * v.w;
    }
    dst[i] = s;
}
__global__ void transpose32(const float* __restrict__ src, float* __restrict__ dst,
                            int R, int C) {
    __shared__ float tile[32][33];
    int bx = blockIdx.x * 32, by = blockIdx.y * 32;
    int tx = threadIdx.x & 31, ty = threadIdx.x >> 5;
#pragma unroll
    for (int i = 0; i < 32; i += 8)
        tile[ty + i][tx] = src[(size_t)(by + ty + i) * C + bx + tx];
    __syncthreads();
#pragma unroll
    for (int i = 0; i < 32; i += 8)
        dst[(size_t)(bx + ty + i) * R + by + tx] = tile[tx][ty + i];
}

// ------------------- MLP GEMM: Y = act(X @ WT^T + bias) --------------------
// CTA tile 128x256, warp 64x64, k64 chunks, cp.async double-buffered,
// ONE __syncthreads per chunk.
#define LDK64   68
#define A64_SZ  (128 * LDK64 * 4)    // 34816
#define B64_SZ  (256 * LDK64 * 4)    // 69632
#define MLP_SMEM (2 * (A64_SZ + B64_SZ))   // 208896

__global__ void __launch_bounds__(256)
mlp_tc(const float* __restrict__ X, const float* __restrict__ WT,
       const float* __restrict__ bias, float* __restrict__ Y,
       int K, int N, int relu) {
    extern __shared__ char sm[];
    const uint32_t sbase = smem_u32(sm);
    const uint32_t Aoff[2] = {0u, A64_SZ};
    const uint32_t Boff[2] = {2 * A64_SZ, 2 * A64_SZ + B64_SZ};

    const int t = threadIdx.x, w = t >> 5, q = (t & 31) >> 2, c = t & 3;
    const int wr = w & 1, wc = w >> 1;
    const int row0 = blockIdx.y * 128, col0 = blockIdx.x * 256;
    const int cr = t >> 4, c16 = (t & 15) * 4;   // 16 rows / pass, 16 f4 / row

    float acc[4][8][4];
#pragma unroll
    for (int mi = 0; mi < 4; mi++)
#pragma unroll
        for (int ni = 0; ni < 8; ni++)
#pragma unroll
            for (int e = 0; e < 4; e++) acc[mi][ni][e] = 0.f;

    auto copy_chunk = [&](int j, int buf) {
#pragma unroll
        for (int i = 0; i < 8; i++) {            // A: 128 rows x 64 k
            int rr = cr + i * 16;
            cp16(sbase + Aoff[buf] + (uint32_t)(rr * LDK64 + c16) * 4,
                 X + (size_t)(row0 + rr) * K + j * 64 + c16);
        }
#pragma unroll
        for (int i = 0; i < 16; i++) {           // B: 256 rows x 64 k
            int rr = cr + i * 16;
            cp16(sbase + Boff[buf] + (uint32_t)(rr * LDK64 + c16) * 4,
                 WT + (size_t)(col0 + rr) * K + j * 64 + c16);
        }
    };

    const int nch = K / 64;
    copy_chunk(0, 0);
    CP_COMMIT();
    for (int j = 0; j < nch; j++) {
        CP_WAIT0();
        __syncthreads();
        if (j + 1 < nch) { copy_chunk(j + 1, (j + 1) & 1); CP_COMMIT(); }
        const float* ab = (const float*)(sm + Aoff[j & 1]);
        const float* bb = (const float*)(sm + Boff[j & 1]);
        const float* aw = ab + (wr * 64 + q) * LDK64 + c;
        const float* bw = bb + (wc * 64 + q) * LDK64 + c;
        compute_k32<LDK64, LDK64>(aw, bw, acc);
        compute_k32<LDK64, LDK64>(aw + 32, bw + 32, acc);
    }

#pragma unroll
    for (int mi = 0; mi < 4; mi++) {
        int rg = row0 + wr * 64 + mi * 16 + q;
#pragma unroll
        for (int ni = 0; ni < 8; ni++) {
            int cg = col0 + wc * 64 + ni * 8 + 2 * c;
            float2 bv = *(const float2*)(bias + cg);
            float v0 = acc[mi][ni][0] + bv.x;
            float v1 = acc[mi][ni][1] + bv.y;
            float v2 = acc[mi][ni][2] + bv.x;
            float v3 = acc[mi][ni][3] + bv.y;
            if (relu) {
                v0 = fmaxf(v0, 0.f); v1 = fmaxf(v1, 0.f);
                v2 = fmaxf(v2, 0.f); v3 = fmaxf(v3, 0.f);
            }
            *(float2*)&Y[(size_t)rg * N + cg] = make_float2(v0, v1);
            *(float2*)&Y[(size_t)(rg + 8) * N + cg] = make_float2(v2, v3);
        }
    }
}

// ---------------- fused distance + partial min ------------------------------
// CTA = (bank quarter, 128-row tile); P tile stationary; bank streamed in
// 256-entry n-tiles x 8 k32 chunks; ONE __syncthreads per chunk.
#define LDK32   36
#define BCH_SZ  (256 * LDK32 * 4)                // 36864
#define AS_LD   260
#define AS_SZ   (128 * AS_LD * 4)                // 133120
#define RED_OFF (AS_SZ + 2 * BCH_SZ)             // 206848
#define DIST_SMEM (RED_OFF + 4 * 128 * 4)        // 208896

__global__ void __launch_bounds__(256)
dist_tc(const float* __restrict__ P, const float* __restrict__ MBp) {
    extern __shared__ char sm[];
    const uint32_t sbase = smem_u32(sm);
    float* As = (float*)sm;
    const uint32_t Boff[2] = {AS_SZ, AS_SZ + BCH_SZ};
    float* red = (float*)(sm + RED_OFF);

    const int t = threadIdx.x, w = t >> 5, q = (t & 31) >> 2, c = t & 3;
    const int wr = w & 1, wc = w >> 1;
    const int row0 = blockIdx.y * 128;
    const int qbase = blockIdx.x * (M_BANK / 4);
    const int cr = t >> 3, c8 = (t & 7) * 4;     // 32 rows / pass, 8 f4 / row

    // stationary P tile [128][260]
#pragma unroll
    for (int i = 0; i < 32; i++) {
        int f = t + i * 256;
        int rr = f >> 6, cq = (f & 63) * 4;
        *(float4*)(As + rr * AS_LD + cq) =
            *(const float4*)(P + (size_t)(row0 + rr) * C_D + cq);
    }

    auto copy_chunk = [&](int jj, int buf) {
        int nt = jj >> 3, kc = jj & 7;
#pragma unroll
        for (int i = 0; i < 8; i++) {            // 256 bank rows x 32 k
            int rr = cr + i * 32;
            cp16(sbase + Boff[buf] + (uint32_t)(rr * LDK32 + c8) * 4,
                 MBp + (size_t)(qbase + nt * 256 + rr) * C_D + kc * 32 + c8);
        }
    };

    float acc[4][8][4];
#pragma unroll
    for (int mi = 0; mi < 4; mi++)
#pragma unroll
        for (int ni = 0; ni < 8; ni++)
#pragma unroll
            for (int e = 0; e < 4; e++) acc[mi][ni][e] = 0.f;
    float runmin[4][2];
#pragma unroll
    for (int mi = 0; mi < 4; mi++) { runmin[mi][0] = 3.402823e38f; runmin[mi][1] = 3.402823e38f; }

    const float* aw0 = As + (wr * 64 + q) * AS_LD + c;

    copy_chunk(0, 0);
    CP_COMMIT();
    const int NCH = (M_BANK / 4 / 256) * 8;      // 128 chunks
    for (int jj = 0; jj < NCH; jj++) {
        CP_WAIT0();
        __syncthreads();                          // also covers As stores (jj=0)
        if (jj + 1 < NCH) { copy_chunk(jj + 1, (jj + 1) & 1); CP_COMMIT(); }
        const int kc = jj & 7;
        const float* bb = (const float*)(sm + Boff[jj & 1]);
        compute_k32<AS_LD, LDK32>(aw0 + kc * 32, bb + (wc * 64 + q) * LDK32 + c, acc);
        if (kc == 7) {
            const int nt = jj >> 3;
            const float* m2p = g_m2 + qbase + nt * 256 + wc * 64 + 2 * c;
#pragma unroll
            for (int mi = 0; mi < 4; mi++) {
                float m0 = runmin[mi][0], m1 = runmin[mi][1];
#pragma unroll
                for (int ni = 0; ni < 8; ni++) {
                    float2 m2v = *(const float2*)(m2p + ni * 8);
                    m0 = fminf(m0, fmaf(-2.f, acc[mi][ni][0], m2v.x));
                    m0 = fminf(m0, fmaf(-2.f, acc[mi][ni][1], m2v.y));
                    m1 = fminf(m1, fmaf(-2.f, acc[mi][ni][2], m2v.x));
                    m1 = fminf(m1, fmaf(-2.f, acc[mi][ni][3], m2v.y));
                    acc[mi][ni][0] = 0.f; acc[mi][ni][1] = 0.f;
                    acc[mi][ni][2] = 0.f; acc[mi][ni][3] = 0.f;
                }
                runmin[mi][0] = m0; runmin[mi][1] = m1;
            }
        }
    }

    // lane reduction (4 lanes share each row), then cross-warp via smem
#pragma unroll
    for (int mi = 0; mi < 4; mi++)
#pragma unroll
        for (int s = 0; s < 2; s++) {
            float v = runmin[mi][s];
            v = fminf(v, __shfl_xor_sync(0xffffffffu, v, 1));
            v = fminf(v, __shfl_xor_sync(0xffffffffu, v, 2));
            if (c == 0) red[wc * 128 + wr * 64 + mi * 16 + s * 8 + q] = v;
        }
    __syncthreads();
    if (t < 128) {
        float m = fminf(fminf(red[t], red[128 + t]), fminf(red[256 + t], red[384 + t]));
        g_pmin[(size_t)blockIdx.x * R_TOTAL + row0 + t] = m;
    }
}

// ------------------------------ combine ------------------------------------
__global__ void combine_kernel(float* __restrict__ out) {
    int r = blockIdx.x * blockDim.x + threadIdx.x;
    float m = fminf(fminf(g_pmin[r], g_pmin[R_TOTAL + r]),
                    fminf(g_pmin[2 * R_TOTAL + r], g_pmin[3 * R_TOTAL + r]));
    out[r] = sqrtf(fmaxf(g_x2[r] + m, 0.f));
}

// ---------------------------------------------------------------------------
extern "C" void kernel_launch(void* const* d_in, const int* in_sizes, int n_in,
                              void* d_out, int out_size) {
    (void)in_sizes; (void)n_in; (void)out_size;
    const float* features = (const float*)d_in[0];
    const float* W1       = (const float*)d_in[1];
    const float* b1       = (const float*)d_in[2];
    const float* W2       = (const float*)d_in[3];
    const float* b2       = (const float*)d_in[4];
    const float* MBp      = (const float*)d_in[5];
    float* out            = (float*)d_out;

    float *H, *Pp, *W1T, *W2T, *m2p, *x2p;
    cudaGetSymbolAddress((void**)&H, g_H);
    cudaGetSymbolAddress((void**)&Pp, g_P);
    cudaGetSymbolAddress((void**)&W1T, g_W1T);
    cudaGetSymbolAddress((void**)&W2T, g_W2T);
    cudaGetSymbolAddress((void**)&m2p, g_m2);
    cudaGetSymbolAddress((void**)&x2p, g_x2);

    cudaFuncSetAttribute(mlp_tc, cudaFuncAttributeMaxDynamicSharedMemorySize, MLP_SMEM);
    cudaFuncSetAttribute(dist_tc, cudaFuncAttributeMaxDynamicSharedMemorySize, DIST_SMEM);

    transpose32<<<dim3(C_HID / 32, C_IN / 32), 256>>>(W1, W1T, C_IN, C_HID);
    transpose32<<<dim3(C_D / 32, C_HID / 32), 256>>>(W2, W2T, C_HID, C_D);
    rowsq_kernel<<<M_BANK / 256, 256>>>(MBp, m2p);
    mlp_tc<<<dim3(C_HID / 256, R_TOTAL / 128), 256, MLP_SMEM>>>(features, W1T, b1, H,
                                                                C_IN, C_HID, 1);
    mlp_tc<<<dim3(C_D / 256, R_TOTAL / 128), 256, MLP_SMEM>>>(H, W2T, b2, Pp,
                                                              C_HID, C_D, 0);
    rowsq_kernel<<<R_TOTAL / 256, 256>>>(Pp, x2p);
    dist_tc<<<dim3(4, R_TOTAL / 128), 256, DIST_SMEM>>>(Pp, MBp);
    combine_kernel<<<R_TOTAL / 256, 256>>>(out);
}